// round 10
// baseline (speedup 1.0000x reference)
#include <cuda_runtime.h>

// Fused y = conv3x3_same(x, w1); z = conv3x3_same(y, w2), [16,1,2048,2048] fp32.
// Register-streaming, incremental accumulation, packed f32x2 FMAs, 8 cols/lane.
// Warp = 256-col strip x 64-row chunk. 4-deep row prefetch queue, loads issued
// immediately after the consuming cvt (max prefetch distance). ulonglong2 row
// loads (aligned f32 pairs free). No smem, no barriers. y forced to 0 outside
// the image (exact two-pass SAME semantics).

#define IMG_H 2048
#define IMG_W 2048
#define ROWS 64
#define STRIPS 8          // 2048 / 256
#define WARPS_PER_CTA 4

typedef unsigned long long u64;

__device__ __forceinline__ u64 pk(float lo, float hi) {
    u64 r; asm("mov.b64 %0, {%1, %2};" : "=l"(r) : "f"(lo), "f"(hi)); return r;
}
__device__ __forceinline__ float lo32(u64 v) { return __uint_as_float((unsigned)v); }
__device__ __forceinline__ float hi32(u64 v) { return __uint_as_float((unsigned)(v >> 32)); }
__device__ __forceinline__ u64 fma2(u64 a, u64 b, u64 c) {
    u64 d; asm("fma.rn.f32x2 %0, %1, %2, %3;" : "=l"(d) : "l"(a), "l"(b), "l"(c)); return d;
}
__device__ __forceinline__ u64 mul2(u64 a, u64 b) {
    u64 d; asm("mul.rn.f32x2 %0, %1, %2;" : "=l"(d) : "l"(a), "l"(b)); return d;
}

struct Raw { ulonglong2 A, B; float2 h; };     // A=(x0,x1|x2,x3) B=(x4,x5|x6,x7)
struct XP  { u64 P[9]; float ea, eb, ec; };    // P[k] = (x[k-1], x[k])
struct YA  { u64 a[4]; float ae; };
struct YQ  { u64 Q[9]; };
struct ZA  { u64 a[4]; };

template <bool SAFE>
__device__ __forceinline__ Raw ldrow(const float*& lp, const float*& hp,
                                     int& lr, bool hOK)
{
    Raw o;
    bool rv = SAFE || ((unsigned)lr < IMG_H);
    if (rv) {
        o.A = __ldg((const ulonglong2*)lp);
        o.B = __ldg((const ulonglong2*)(lp + 4));
    } else {
        o.A = make_ulonglong2(0ull, 0ull);
        o.B = make_ulonglong2(0ull, 0ull);
    }
    if (hOK && rv) o.h = __ldg((const float2*)hp);
    else           o.h = make_float2(0.f, 0.f);
    lp += IMG_W; hp += IMG_W;
    if (!SAFE) lr++;
    return o;
}

__device__ __forceinline__ XP cvt(const Raw& p, int lane)
{
    float v0 = lo32(p.A.x), v1 = hi32(p.A.x), v2 = lo32(p.A.y), v3 = hi32(p.A.y);
    float v4 = lo32(p.B.x), v5 = hi32(p.B.x), v6 = lo32(p.B.y), v7 = hi32(p.B.y);
    float up = __shfl_up_sync(0xffffffffu, v7, 1);
    float dn = __shfl_down_sync(0xffffffffu, v0, 1);
    float xm1 = (lane == 0)  ? p.h.y : up;    // x[8g-1]
    float xp8 = (lane == 31) ? p.h.x : dn;    // x[8g+8]
    XP x;
    x.P[0] = pk(xm1, v0);
    x.P[1] = p.A.x;
    x.P[2] = pk(v1, v2);
    x.P[3] = p.A.y;
    x.P[4] = pk(v3, v4);
    x.P[5] = p.B.x;
    x.P[6] = pk(v5, v6);
    x.P[7] = p.B.y;
    x.P[8] = pk(v7, xp8);
    x.ea = (lane == 0) ? p.h.x : v7;
    x.eb = (lane == 0) ? xm1   : xp8;
    x.ec = (lane == 0) ? v0    : p.h.y;
    return x;
}

template <int A, bool FIRST>
__device__ __forceinline__ void addY(YA& y, const XP& x, const u64* W)
{
#pragma unroll
    for (int j = 0; j < 4; j++) {
        u64 t = FIRST ? mul2(W[3*A], x.P[2*j])
                      : fma2(W[3*A], x.P[2*j], y.a[j]);
        t = fma2(W[3*A+1], x.P[2*j+1], t);
        y.a[j] = fma2(W[3*A+2], x.P[2*j+2], t);
    }
    float e = FIRST ? (lo32(W[3*A]) * x.ea)
                    : fmaf(lo32(W[3*A]), x.ea, y.ae);
    e = fmaf(lo32(W[3*A+1]), x.eb, e);
    y.ae = fmaf(lo32(W[3*A+2]), x.ec, e);
}

template <bool SAFE>
__device__ __forceinline__ YQ fin(YA y, bool valid, bool killE, int lane)
{
    if (!SAFE && !valid) {
#pragma unroll
        for (int j = 0; j < 4; j++) y.a[j] = 0ull;
        y.ae = 0.f;
    }
    if (killE) y.ae = 0.f;
    float y0 = lo32(y.a[0]), y7 = hi32(y.a[3]);
    float up = __shfl_up_sync(0xffffffffu, y7, 1);
    float dn = __shfl_down_sync(0xffffffffu, y0, 1);
    float ym1 = (lane == 0)  ? y.ae : up;
    float yp8 = (lane == 31) ? y.ae : dn;
    YQ q;
    q.Q[0] = pk(ym1, y0);
#pragma unroll
    for (int j = 0; j < 4; j++) q.Q[2*j+1] = y.a[j];
#pragma unroll
    for (int j = 1; j < 4; j++) q.Q[2*j] = pk(hi32(y.a[j-1]), lo32(y.a[j]));
    q.Q[8] = pk(y7, yp8);
    return q;
}

template <int A, bool FIRST>
__device__ __forceinline__ void addZ(ZA& z, const YQ& q, const u64* W)
{
#pragma unroll
    for (int j = 0; j < 4; j++) {
        u64 t = FIRST ? mul2(W[3*A], q.Q[2*j])
                      : fma2(W[3*A], q.Q[2*j], z.a[j]);
        t = fma2(W[3*A+1], q.Q[2*j+1], t);
        z.a[j] = fma2(W[3*A+2], q.Q[2*j+2], t);
    }
}

__device__ __forceinline__ void stz(float* p, const ZA& z)
{
    *(float4*)p       = make_float4(lo32(z.a[0]), hi32(z.a[0]),
                                    lo32(z.a[1]), hi32(z.a[1]));
    *(float4*)(p + 4) = make_float4(lo32(z.a[2]), hi32(z.a[2]),
                                    lo32(z.a[3]), hi32(z.a[3]));
}

template <bool SAFE>
__device__ __forceinline__ void run(const float* __restrict__ xb,
                                    float* __restrict__ ob,
                                    const float* __restrict__ w1g,
                                    const float* __restrict__ w2g,
                                    int c0, int R0, int lane, bool lE, bool rE)
{
    u64 W1[9], W2[9];
#pragma unroll
    for (int i = 0; i < 9; i++) {
        float a = __ldg(w1g + i); W1[i] = pk(a, a);
        float b = __ldg(w2g + i); W2[i] = pk(b, b);
    }
    const bool hOK   = (lane == 0 && !lE) || (lane == 31 && !rE);
    const bool killE = (lane == 0 && lE) || (lane == 31 && rE);

    const float* lp = xb + (size_t)(R0 - 2) * IMG_W + c0 + 8 * lane;
    const float* hp = lp + ((lane == 31) ? 8 : -2);
    float*     orow = ob + (size_t)R0 * IMG_W + c0 + 8 * lane;
    int lr = R0 - 2;
    int r  = R0;

    // ---- Prologue: fill 4-deep queue with rows R0-2..R0+1 ----
    Raw q0 = ldrow<SAFE>(lp, hp, lr, hOK);
    Raw q1 = ldrow<SAFE>(lp, hp, lr, hOK);
    Raw q2 = ldrow<SAFE>(lp, hp, lr, hOK);
    Raw q3 = ldrow<SAFE>(lp, hp, lr, hOK);

    YA t1, t2, ya, yb, yc;
    ZA za, zb, zc;

    XP A = cvt(q0, lane); q0 = ldrow<SAFE>(lp, hp, lr, hOK);   // row R0+2
    addY<0, true >(t1, A, W1);
    XP B = cvt(q1, lane); q1 = ldrow<SAFE>(lp, hp, lr, hOK);   // row R0+3
    addY<1, false>(t1, B, W1);
    addY<0, true >(t2, B, W1);
    XP C = cvt(q2, lane); q2 = ldrow<SAFE>(lp, hp, lr, hOK);   // row R0+4
    addY<2, false>(t1, C, W1);
    addY<1, false>(t2, C, W1);
    addY<0, true >(ya, C, W1);
    YQ Q = fin<SAFE>(t1, (unsigned)(R0 - 1) < IMG_H, killE, lane);
    addZ<0, true >(za, Q, W2);
    XP D = cvt(q3, lane); q3 = ldrow<SAFE>(lp, hp, lr, hOK);   // row R0+5
    addY<2, false>(t2, D, W1);
    addY<1, false>(ya, D, W1);
    addY<0, true >(yb, D, W1);
    Q = fin<SAFE>(t2, true, killE, lane);
    addZ<1, false>(za, Q, W2);
    addZ<0, true >(zb, Q, W2);

    // ---- Steady state: step r consumes row r+2, loads row r+6, stores z(r).
    //      Load is issued IMMEDIATELY after cvt, before the compute body. ----
#define STEP(P, Y0, Y1, Y2, Z0, Z1, Z2)                                       \
    do {                                                                      \
        XP X = cvt(P, lane);                                                  \
        P = ldrow<SAFE>(lp, hp, lr, hOK);                                     \
        addY<2, false>(Y0, X, W1);                                            \
        addY<1, false>(Y1, X, W1);                                            \
        addY<0, true >(Y2, X, W1);                                            \
        YQ Qs = fin<SAFE>(Y0, (unsigned)(r + 1) < IMG_H, killE, lane);        \
        addZ<2, false>(Z0, Qs, W2);                                           \
        addZ<1, false>(Z1, Qs, W2);                                           \
        addZ<0, true >(Z2, Qs, W2);                                           \
        stz(orow, Z0);                                                        \
        orow += IMG_W; r++;                                                   \
    } while (0)

#define STEPNL(P, Y0, Y1, Y2, Z0, Z1, Z2)                                     \
    do {                                                                      \
        XP X = cvt(P, lane);                                                  \
        addY<2, false>(Y0, X, W1);                                            \
        addY<1, false>(Y1, X, W1);                                            \
        addY<0, true >(Y2, X, W1);                                            \
        YQ Qs = fin<SAFE>(Y0, (unsigned)(r + 1) < IMG_H, killE, lane);        \
        addZ<2, false>(Z0, Qs, W2);                                           \
        addZ<1, false>(Z1, Qs, W2);                                           \
        addZ<0, true >(Z2, Qs, W2);                                           \
        stz(orow, Z0);                                                        \
        orow += IMG_W; r++;                                                   \
    } while (0)

    // 60 loading steps (5 x 12-step LCM block; queue period 4, Y/Z period 3),
    // then 4 no-load steps. Total 64. Last load: step 59 -> row R0+65.
#pragma unroll 1
    for (int i = 0; i < 5; i++) {
        STEP(q0, ya, yb, yc, za, zb, zc);
        STEP(q1, yb, yc, ya, zb, zc, za);
        STEP(q2, yc, ya, yb, zc, za, zb);
        STEP(q3, ya, yb, yc, za, zb, zc);
        STEP(q0, yb, yc, ya, zb, zc, za);
        STEP(q1, yc, ya, yb, zc, za, zb);
        STEP(q2, ya, yb, yc, za, zb, zc);
        STEP(q3, yb, yc, ya, zb, zc, za);
        STEP(q0, yc, ya, yb, zc, za, zb);
        STEP(q1, ya, yb, yc, za, zb, zc);
        STEP(q2, yb, yc, ya, zb, zc, za);
        STEP(q3, yc, ya, yb, zc, za, zb);
    }
    STEPNL(q0, ya, yb, yc, za, zb, zc);   // step 60
    STEPNL(q1, yb, yc, ya, zb, zc, za);   // step 61
    STEPNL(q2, yc, ya, yb, zc, za, zb);   // step 62
    STEPNL(q3, ya, yb, yc, za, zb, zc);   // step 63
#undef STEP
#undef STEPNL
}

__global__ __launch_bounds__(WARPS_PER_CTA * 32, 3)
void conv2x_q4(const float* __restrict__ x, const float* __restrict__ w1g,
               const float* __restrict__ w2g, float* __restrict__ out)
{
    const int lane  = threadIdx.x & 31;
    const int wrp   = threadIdx.x >> 5;
    const int strip = blockIdx.x;                       // 0..7
    const int chunk = blockIdx.y * WARPS_PER_CTA + wrp; // 0..31
    const int c0 = strip * 256;
    const int R0 = chunk * ROWS;
    const bool lE = (strip == 0);
    const bool rE = (strip == STRIPS - 1);

    const float* xb = x   + (size_t)blockIdx.z * ((size_t)IMG_H * IMG_W);
    float*       ob = out + (size_t)blockIdx.z * ((size_t)IMG_H * IMG_W);

    if (chunk != 0 && chunk != (IMG_H / ROWS) - 1)
        run<true >(xb, ob, w1g, w2g, c0, R0, lane, lE, rE);
    else
        run<false>(xb, ob, w1g, w2g, c0, R0, lane, lE, rE);
}

extern "C" void kernel_launch(void* const* d_in, const int* in_sizes, int n_in,
                              void* d_out, int out_size)
{
    const float* x  = (const float*)d_in[0];
    const float* w1 = (const float*)d_in[1];
    const float* w2 = (const float*)d_in[2];
    float* out = (float*)d_out;

    const int B = in_sizes[0] / (IMG_H * IMG_W);            // 16
    dim3 grid(STRIPS, (IMG_H / ROWS) / WARPS_PER_CTA, B);   // 8 x 8 x 16 = 1024
    conv2x_q4<<<grid, WARPS_PER_CTA * 32>>>(x, w1, w2, out);
}

// round 11
// speedup vs baseline: 1.1355x; 1.1355x over previous
#include <cuda_runtime.h>
#include <cstdint>

// Fused y = conv3x3_same(x, w1); z = conv3x3_same(y, w2), [16,1,2048,2048] fp32.
// Warp = 256-col strip x 64-row chunk, 8 cols/lane. X rows stream through a
// warp-private 6-slot cp.async smem ring (halo columns included in the slot,
// so cvt needs no shuffles). Incremental accumulation + packed f32x2 FMAs
// (identical math to the round-7 kernel). y forced to 0 outside the image.

#define IMG_H 2048
#define IMG_W 2048
#define ROWS 64
#define STRIPS 8
#define WARPS_PER_CTA 4
#define RING 6
#define ROWB 1088                  // slot: 8 pad + 256 data + 8 pad floats
#define WSMEM (RING * ROWB)        // 6528 B per warp

typedef unsigned long long u64;

__device__ __forceinline__ u64 pk(float lo, float hi) {
    u64 r; asm("mov.b64 %0, {%1, %2};" : "=l"(r) : "f"(lo), "f"(hi)); return r;
}
__device__ __forceinline__ float lo32(u64 v) { return __uint_as_float((unsigned)v); }
__device__ __forceinline__ float hi32(u64 v) { return __uint_as_float((unsigned)(v >> 32)); }
__device__ __forceinline__ u64 fma2(u64 a, u64 b, u64 c) {
    u64 d; asm("fma.rn.f32x2 %0, %1, %2, %3;" : "=l"(d) : "l"(a), "l"(b), "l"(c)); return d;
}
__device__ __forceinline__ u64 mul2(u64 a, u64 b) {
    u64 d; asm("mul.rn.f32x2 %0, %1, %2;" : "=l"(d) : "l"(a), "l"(b)); return d;
}
__device__ __forceinline__ void cpa16(uint32_t d, const float* s) {
    asm volatile("cp.async.cg.shared.global [%0], [%1], 16;" :: "r"(d), "l"(s));
}

struct XP { u64 P[9]; float ea, eb, ec; };   // P[k] = (x[k-1], x[k]) per lane
struct YA { u64 a[4]; float ae; };
struct YQ { u64 Q[9]; };
struct ZA { u64 a[4]; };

// Issue one x row into a ring slot. Invalid rows (outside image) are
// zero-filled with STS instead (unsafe chunks only).
template <bool SAFE>
__device__ __forceinline__ void issue_row(char* slot, uint32_t slot_u,
                                          const float* src, int lane,
                                          bool lE, bool rE, bool inimg)
{
    if (SAFE || inimg) {
        uint32_t d = slot_u + 32 + lane * 32;
        cpa16(d,      src + 8 * lane);
        cpa16(d + 16, src + 8 * lane + 4);
        if (lane == 0  && !lE) cpa16(slot_u + 16,   src - 4);
        if (lane == 31 && !rE) cpa16(slot_u + 1056, src + 256);
    } else {
        float4 z = make_float4(0.f, 0.f, 0.f, 0.f);
        *(float4*)(slot + 32 + lane * 32) = z;
        *(float4*)(slot + 48 + lane * 32) = z;
        if (lane == 0)  *(float4*)(slot + 16)   = z;
        if (lane == 31) *(float4*)(slot + 1056) = z;
    }
}

// Build packed x pairs from a ready ring slot. No shuffles: halo read from smem.
__device__ __forceinline__ XP cvts(const char* slot, int lane)
{
    const float* sp = (const float*)(slot + 32 + lane * 32);
    float4 a = *(const float4*)sp;
    float4 b = *(const float4*)(sp + 4);
    float xm1 = sp[-1];
    float xp8 = sp[8];
    float ee  = sp[(lane == 0) ? -2 : 9];
    XP x;
    x.P[0] = pk(xm1, a.x); x.P[1] = pk(a.x, a.y); x.P[2] = pk(a.y, a.z);
    x.P[3] = pk(a.z, a.w); x.P[4] = pk(a.w, b.x); x.P[5] = pk(b.x, b.y);
    x.P[6] = pk(b.y, b.z); x.P[7] = pk(b.z, b.w); x.P[8] = pk(b.w, xp8);
    x.ea = (lane == 0) ? ee  : b.w;    // x[edge-1]
    x.eb = (lane == 0) ? xm1 : xp8;    // x[edge]
    x.ec = (lane == 0) ? a.x : ee;     // x[edge+1]
    return x;
}

template <int A, bool FIRST>
__device__ __forceinline__ void addY(YA& y, const XP& x, const u64* W)
{
#pragma unroll
    for (int j = 0; j < 4; j++) {
        u64 t = FIRST ? mul2(W[3*A], x.P[2*j])
                      : fma2(W[3*A], x.P[2*j], y.a[j]);
        t = fma2(W[3*A+1], x.P[2*j+1], t);
        y.a[j] = fma2(W[3*A+2], x.P[2*j+2], t);
    }
    float e = FIRST ? (lo32(W[3*A]) * x.ea)
                    : fmaf(lo32(W[3*A]), x.ea, y.ae);
    e = fmaf(lo32(W[3*A+1]), x.eb, e);
    y.ae = fmaf(lo32(W[3*A+2]), x.ec, e);
}

template <bool SAFE>
__device__ __forceinline__ YQ fin(YA y, bool valid, bool killE, int lane)
{
    if (!SAFE && !valid) {
#pragma unroll
        for (int j = 0; j < 4; j++) y.a[j] = 0ull;
        y.ae = 0.f;
    }
    if (killE) y.ae = 0.f;
    float y0 = lo32(y.a[0]), y7 = hi32(y.a[3]);
    float up = __shfl_up_sync(0xffffffffu, y7, 1);
    float dn = __shfl_down_sync(0xffffffffu, y0, 1);
    float ym1 = (lane == 0)  ? y.ae : up;
    float yp8 = (lane == 31) ? y.ae : dn;
    YQ q;
    q.Q[0] = pk(ym1, y0);
#pragma unroll
    for (int j = 0; j < 4; j++) q.Q[2*j+1] = y.a[j];
#pragma unroll
    for (int j = 1; j < 4; j++) q.Q[2*j] = pk(hi32(y.a[j-1]), lo32(y.a[j]));
    q.Q[8] = pk(y7, yp8);
    return q;
}

template <int A, bool FIRST>
__device__ __forceinline__ void addZ(ZA& z, const YQ& q, const u64* W)
{
#pragma unroll
    for (int j = 0; j < 4; j++) {
        u64 t = FIRST ? mul2(W[3*A], q.Q[2*j])
                      : fma2(W[3*A], q.Q[2*j], z.a[j]);
        t = fma2(W[3*A+1], q.Q[2*j+1], t);
        z.a[j] = fma2(W[3*A+2], q.Q[2*j+2], t);
    }
}

__device__ __forceinline__ void stz(float* p, const ZA& z)
{
    *(float4*)p       = make_float4(lo32(z.a[0]), hi32(z.a[0]),
                                    lo32(z.a[1]), hi32(z.a[1]));
    *(float4*)(p + 4) = make_float4(lo32(z.a[2]), hi32(z.a[2]),
                                    lo32(z.a[3]), hi32(z.a[3]));
}

template <bool SAFE>
__device__ __forceinline__ void run(char* wb, uint32_t wb_u,
                                    const float* __restrict__ xb,
                                    float* __restrict__ ob,
                                    const float* __restrict__ w1g,
                                    const float* __restrict__ w2g,
                                    int c0, int R0, int lane, bool lE, bool rE)
{
    u64 W1[9], W2[9];
#pragma unroll
    for (int i = 0; i < 9; i++) {
        float a = __ldg(w1g + i); W1[i] = pk(a, a);
        float b = __ldg(w2g + i); W2[i] = pk(b, b);
    }
    const bool killE = (lane == 0 && lE) || (lane == 31 && rE);

    // Zero pads once (needed only for edge strips; harmless otherwise).
    if (lane < RING) {
        float4 z = make_float4(0.f, 0.f, 0.f, 0.f);
        *(float4*)(wb + lane * ROWB + 16)   = z;
        *(float4*)(wb + lane * ROWB + 1056) = z;
    }

    // ---- Prologue: issue rows R0-2 .. R0+2 into slots 0..4 ----
    const float* srcp = xb + (size_t)(R0 - 2) * IMG_W + c0;
    int irow = R0 - 2;
#pragma unroll
    for (int s = 0; s < 5; s++) {
        issue_row<SAFE>(wb + s * ROWB, wb_u + s * ROWB, srcp, lane, lE, rE,
                        (unsigned)irow < IMG_H);
        asm volatile("cp.async.commit_group;");
        srcp += IMG_W; irow++;
    }

    int coff = 0;              // consume slot byte offset
    int ioff = 5 * ROWB;       // next issue slot byte offset
    int nIssue = 63;           // rows R0+3 .. R0+65 remain to be issued
    float* orow = ob + (size_t)R0 * IMG_W + c0 + 8 * lane;
    int r = R0;

    // CONSUME: wait for oldest needed row, read+pack it, issue next row.
#define CONSUME(XV)                                                           \
    do {                                                                      \
        asm volatile("cp.async.wait_group 4;");                               \
        __syncwarp();                                                         \
        XV = cvts(wb + coff, lane);                                           \
        coff += ROWB; if (coff == WSMEM) coff = 0;                            \
        if (nIssue > 0) {                                                     \
            issue_row<SAFE>(wb + ioff, wb_u + ioff, srcp, lane, lE, rE,       \
                            (unsigned)irow < IMG_H);                          \
            nIssue--; srcp += IMG_W; irow++;                                  \
            ioff += ROWB; if (ioff == WSMEM) ioff = 0;                        \
        }                                                                     \
        asm volatile("cp.async.commit_group;");                               \
    } while (0)

    YA t1, t2, ya, yb, yc;
    ZA za, zb, zc;

    XP A; CONSUME(A);                                  // row R0-2
    addY<0, true >(t1, A, W1);
    XP B; CONSUME(B);                                  // row R0-1
    addY<1, false>(t1, B, W1);
    addY<0, true >(t2, B, W1);
    XP C; CONSUME(C);                                  // row R0
    addY<2, false>(t1, C, W1);
    addY<1, false>(t2, C, W1);
    addY<0, true >(ya, C, W1);
    YQ Q = fin<SAFE>(t1, (unsigned)(R0 - 1) < IMG_H, killE, lane);
    addZ<0, true >(za, Q, W2);
    XP D; CONSUME(D);                                  // row R0+1
    addY<2, false>(t2, D, W1);
    addY<1, false>(ya, D, W1);
    addY<0, true >(yb, D, W1);
    Q = fin<SAFE>(t2, true, killE, lane);
    addZ<1, false>(za, Q, W2);
    addZ<0, true >(zb, Q, W2);

    // ---- Steady state: step r consumes row r+2, stores z(r) ----
#define STEP(Y0, Y1, Y2, Z0, Z1, Z2)                                          \
    do {                                                                      \
        XP X; CONSUME(X);                                                     \
        addY<2, false>(Y0, X, W1);                                            \
        addY<1, false>(Y1, X, W1);                                            \
        addY<0, true >(Y2, X, W1);                                            \
        YQ Qs = fin<SAFE>(Y0, (unsigned)(r + 1) < IMG_H, killE, lane);        \
        addZ<2, false>(Z0, Qs, W2);                                           \
        addZ<1, false>(Z1, Qs, W2);                                           \
        addZ<0, true >(Z2, Qs, W2);                                           \
        stz(orow, Z0);                                                        \
        orow += IMG_W; r++;                                                   \
    } while (0)

#pragma unroll 1
    for (int i = 0; i < 21; i++) {                     // 63 rows
        STEP(ya, yb, yc, za, zb, zc);
        STEP(yb, yc, ya, zb, zc, za);
        STEP(yc, ya, yb, zc, za, zb);
    }
    STEP(ya, yb, yc, za, zb, zc);                      // row 64
#undef STEP
#undef CONSUME
}

__global__ __launch_bounds__(WARPS_PER_CTA * 32, 4)
void conv2x_ring(const float* __restrict__ x, const float* __restrict__ w1g,
                 const float* __restrict__ w2g, float* __restrict__ out)
{
    __shared__ char smem[WARPS_PER_CTA * WSMEM];       // 26112 B

    const int lane  = threadIdx.x & 31;
    const int wrp   = threadIdx.x >> 5;
    const int strip = blockIdx.x;                       // 0..7
    const int chunk = blockIdx.y * WARPS_PER_CTA + wrp; // 0..31
    const int c0 = strip * 256;
    const int R0 = chunk * ROWS;
    const bool lE = (strip == 0);
    const bool rE = (strip == STRIPS - 1);

    char* wb = smem + wrp * WSMEM;
    uint32_t wb_u = (uint32_t)__cvta_generic_to_shared(wb);

    const float* xb = x   + (size_t)blockIdx.z * ((size_t)IMG_H * IMG_W);
    float*       ob = out + (size_t)blockIdx.z * ((size_t)IMG_H * IMG_W);

    if (chunk != 0 && chunk != (IMG_H / ROWS) - 1)
        run<true >(wb, wb_u, xb, ob, w1g, w2g, c0, R0, lane, lE, rE);
    else
        run<false>(wb, wb_u, xb, ob, w1g, w2g, c0, R0, lane, lE, rE);
}

extern "C" void kernel_launch(void* const* d_in, const int* in_sizes, int n_in,
                              void* d_out, int out_size)
{
    const float* x  = (const float*)d_in[0];
    const float* w1 = (const float*)d_in[1];
    const float* w2 = (const float*)d_in[2];
    float* out = (float*)d_out;

    const int B = in_sizes[0] / (IMG_H * IMG_W);            // 16
    dim3 grid(STRIPS, (IMG_H / ROWS) / WARPS_PER_CTA, B);   // 8 x 8 x 16 = 1024
    conv2x_ring<<<grid, WARPS_PER_CTA * 32>>>(x, w1, w2, out);
}

// round 12
// speedup vs baseline: 1.1832x; 1.0421x over previous
#include <cuda_runtime.h>
#include <cstdint>

// Fused y = conv3x3_same(x, w1); z = conv3x3_same(y, w2), [16,1,2048,2048] fp32.
// Warp = 256-col strip x 64-row chunk, 8 cols/lane. X rows stream through a
// warp-private 6-slot cp.async smem ring. Rows read back as ulonglong2 (aligned
// f32 pairs free); horizontal halo via warp shuffles + lanes 0/31 self-loaded
// 8B halo. Consume of row r+3 is issued BEFORE fin/addZ of z(r) so LDS latency
// overlaps compute. Incremental accumulation + packed f32x2 FMAs.
// y forced to 0 outside the image (exact two-pass SAME semantics).

#define IMG_H 2048
#define IMG_W 2048
#define ROWS 64
#define STRIPS 8
#define WARPS_PER_CTA 4
#define RING 6
#define ROWB 1088                  // 8 pad + 256 data + 8 pad floats
#define WSMEM (RING * ROWB)

typedef unsigned long long u64;

__device__ __forceinline__ u64 pk(float lo, float hi) {
    u64 r; asm("mov.b64 %0, {%1, %2};" : "=l"(r) : "f"(lo), "f"(hi)); return r;
}
__device__ __forceinline__ float lo32(u64 v) { return __uint_as_float((unsigned)v); }
__device__ __forceinline__ float hi32(u64 v) { return __uint_as_float((unsigned)(v >> 32)); }
__device__ __forceinline__ u64 fma2(u64 a, u64 b, u64 c) {
    u64 d; asm("fma.rn.f32x2 %0, %1, %2, %3;" : "=l"(d) : "l"(a), "l"(b), "l"(c)); return d;
}
__device__ __forceinline__ u64 mul2(u64 a, u64 b) {
    u64 d; asm("mul.rn.f32x2 %0, %1, %2;" : "=l"(d) : "l"(a), "l"(b)); return d;
}
__device__ __forceinline__ void cpa16(uint32_t d, const float* s) {
    asm volatile("cp.async.cg.shared.global [%0], [%1], 16;" :: "r"(d), "l"(s));
}
__device__ __forceinline__ void cpa8(uint32_t d, const float* s) {
    asm volatile("cp.async.ca.shared.global [%0], [%1], 8;" :: "r"(d), "l"(s));
}

struct XP { u64 P[9]; float ea, eb, ec; };
struct YA { u64 a[4]; float ae; };
struct YQ { u64 Q[9]; };
struct ZA { u64 a[4]; };

// Issue one x row into a ring slot. Out-of-image rows zero-filled via STS.
// Every lane writes/loads only regions it later reads itself (no cross-lane
// smem dependencies -> no __syncwarp needed).
template <bool SAFE>
__device__ __forceinline__ void issue_row(char* slot, uint32_t slot_u,
                                          const float* src, int lane,
                                          bool lE, bool rE, bool inimg)
{
    if (SAFE || inimg) {
        uint32_t d = slot_u + 32 + lane * 32;
        cpa16(d,      src + 8 * lane);
        cpa16(d + 16, src + 8 * lane + 4);
        if (lane == 0  && !lE) cpa8(slot_u + 24,   src - 2);     // x[-2],x[-1]
        if (lane == 31 && !rE) cpa8(slot_u + 1056, src + 256);   // x[256],x[257]
    } else {
        float4 z4 = make_float4(0.f, 0.f, 0.f, 0.f);
        *(float4*)(slot + 32 + lane * 32) = z4;
        *(float4*)(slot + 48 + lane * 32) = z4;
        if (lane == 0)  *(float2*)(slot + 24)   = make_float2(0.f, 0.f);
        if (lane == 31) *(float2*)(slot + 1056) = make_float2(0.f, 0.f);
    }
}

// Read a ready slot: 2x LDS.128 as ulonglong2 (aligned pairs free) + own halo.
__device__ __forceinline__ XP cvts(const char* slot, int lane)
{
    const float* sf = (const float*)slot;
    const ulonglong2* dp = (const ulonglong2*)(sf + 8 + lane * 8);
    ulonglong2 A = dp[0], B = dp[1];
    float2 h = *(const float2*)(sf + ((lane == 31) ? 264 : 6));  // used by 0/31 only
    float v0 = lo32(A.x), v1 = hi32(A.x), v2 = lo32(A.y), v3 = hi32(A.y);
    float v4 = lo32(B.x), v5 = hi32(B.x), v6 = lo32(B.y), v7 = hi32(B.y);
    float up = __shfl_up_sync(0xffffffffu, v7, 1);
    float dn = __shfl_down_sync(0xffffffffu, v0, 1);
    float xm1 = (lane == 0)  ? h.y : up;
    float xp8 = (lane == 31) ? h.x : dn;
    XP x;
    x.P[0] = pk(xm1, v0);
    x.P[1] = A.x;
    x.P[2] = pk(v1, v2);
    x.P[3] = A.y;
    x.P[4] = pk(v3, v4);
    x.P[5] = B.x;
    x.P[6] = pk(v5, v6);
    x.P[7] = B.y;
    x.P[8] = pk(v7, xp8);
    x.ea = (lane == 0) ? h.x : v7;
    x.eb = (lane == 0) ? xm1 : xp8;
    x.ec = (lane == 0) ? v0  : h.y;
    return x;
}

template <int A, bool FIRST>
__device__ __forceinline__ void addY(YA& y, const XP& x, const u64* W)
{
#pragma unroll
    for (int j = 0; j < 4; j++) {
        u64 t = FIRST ? mul2(W[3*A], x.P[2*j])
                      : fma2(W[3*A], x.P[2*j], y.a[j]);
        t = fma2(W[3*A+1], x.P[2*j+1], t);
        y.a[j] = fma2(W[3*A+2], x.P[2*j+2], t);
    }
    float e = FIRST ? (lo32(W[3*A]) * x.ea)
                    : fmaf(lo32(W[3*A]), x.ea, y.ae);
    e = fmaf(lo32(W[3*A+1]), x.eb, e);
    y.ae = fmaf(lo32(W[3*A+2]), x.ec, e);
}

template <bool SAFE>
__device__ __forceinline__ YQ fin(YA y, bool valid, bool killE, int lane)
{
    if (!SAFE && !valid) {
#pragma unroll
        for (int j = 0; j < 4; j++) y.a[j] = 0ull;
        y.ae = 0.f;
    }
    if (killE) y.ae = 0.f;
    float y0 = lo32(y.a[0]), y7 = hi32(y.a[3]);
    float up = __shfl_up_sync(0xffffffffu, y7, 1);
    float dn = __shfl_down_sync(0xffffffffu, y0, 1);
    float ym1 = (lane == 0)  ? y.ae : up;
    float yp8 = (lane == 31) ? y.ae : dn;
    YQ q;
    q.Q[0] = pk(ym1, y0);
#pragma unroll
    for (int j = 0; j < 4; j++) q.Q[2*j+1] = y.a[j];
#pragma unroll
    for (int j = 1; j < 4; j++) q.Q[2*j] = pk(hi32(y.a[j-1]), lo32(y.a[j]));
    q.Q[8] = pk(y7, yp8);
    return q;
}

template <int A, bool FIRST>
__device__ __forceinline__ void addZ(ZA& z, const YQ& q, const u64* W)
{
#pragma unroll
    for (int j = 0; j < 4; j++) {
        u64 t = FIRST ? mul2(W[3*A], q.Q[2*j])
                      : fma2(W[3*A], q.Q[2*j], z.a[j]);
        t = fma2(W[3*A+1], q.Q[2*j+1], t);
        z.a[j] = fma2(W[3*A+2], q.Q[2*j+2], t);
    }
}

__device__ __forceinline__ void stz(float* p, const ZA& z)
{
    *(float4*)p       = make_float4(lo32(z.a[0]), hi32(z.a[0]),
                                    lo32(z.a[1]), hi32(z.a[1]));
    *(float4*)(p + 4) = make_float4(lo32(z.a[2]), hi32(z.a[2]),
                                    lo32(z.a[3]), hi32(z.a[3]));
}

template <bool SAFE>
__device__ __forceinline__ void run(char* wb, uint32_t wb_u,
                                    const float* __restrict__ xb,
                                    float* __restrict__ ob,
                                    const float* __restrict__ w1g,
                                    const float* __restrict__ w2g,
                                    int c0, int R0, int lane, bool lE, bool rE)
{
    u64 W1[9], W2[9];
#pragma unroll
    for (int i = 0; i < 9; i++) {
        float a = __ldg(w1g + i); W1[i] = pk(a, a);
        float b = __ldg(w2g + i); W2[i] = pk(b, b);
    }
    const bool killE = (lane == 0 && lE) || (lane == 31 && rE);

    // Zero halo pads once; each pad is zeroed by the lane that later reads it.
    if (lane == 0) {
#pragma unroll
        for (int s = 0; s < RING; s++)
            *(float2*)(wb + s * ROWB + 24) = make_float2(0.f, 0.f);
    }
    if (lane == 31) {
#pragma unroll
        for (int s = 0; s < RING; s++)
            *(float2*)(wb + s * ROWB + 1056) = make_float2(0.f, 0.f);
    }

    // ---- Prologue: issue rows R0-2 .. R0+2 into slots 0..4 ----
    const float* srcp = xb + (size_t)(R0 - 2) * IMG_W + c0;
    int irow = R0 - 2;
#pragma unroll
    for (int s = 0; s < 5; s++) {
        issue_row<SAFE>(wb + s * ROWB, wb_u + s * ROWB, srcp, lane, lE, rE,
                        (unsigned)irow < IMG_H);
        asm volatile("cp.async.commit_group;");
        srcp += IMG_W; irow++;
    }

    int coff = 0;
    int ioff = 5 * ROWB;
    int nIssue = 63;            // rows R0+3 .. R0+65
    float* orow = ob + (size_t)R0 * IMG_W + c0 + 8 * lane;
    int r = R0;

#define CONSUME(XV)                                                           \
    do {                                                                      \
        asm volatile("cp.async.wait_group 4;");                               \
        XV = cvts(wb + coff, lane);                                           \
        coff += ROWB; if (coff == WSMEM) coff = 0;                            \
        if (nIssue > 0) {                                                     \
            issue_row<SAFE>(wb + ioff, wb_u + ioff, srcp, lane, lE, rE,       \
                            (unsigned)irow < IMG_H);                          \
            nIssue--; srcp += IMG_W; irow++;                                  \
            ioff += ROWB; if (ioff == WSMEM) ioff = 0;                        \
        }                                                                     \
        asm volatile("cp.async.commit_group;");                               \
    } while (0)

    YA t1, t2, ya, yb, yc;
    ZA za, zb, zc;

    XP A; CONSUME(A);                                  // row R0-2
    addY<0, true >(t1, A, W1);
    XP B; CONSUME(B);                                  // row R0-1
    addY<1, false>(t1, B, W1);
    addY<0, true >(t2, B, W1);
    XP C; CONSUME(C);                                  // row R0
    addY<2, false>(t1, C, W1);
    addY<1, false>(t2, C, W1);
    addY<0, true >(ya, C, W1);
    YQ Q = fin<SAFE>(t1, (unsigned)(R0 - 1) < IMG_H, killE, lane);
    addZ<0, true >(za, Q, W2);
    XP D; CONSUME(D);                                  // row R0+1
    addY<2, false>(t2, D, W1);
    addY<1, false>(ya, D, W1);
    addY<0, true >(yb, D, W1);
    Q = fin<SAFE>(t2, true, killE, lane);
    addZ<1, false>(za, Q, W2);
    addZ<0, true >(zb, Q, W2);

    XP X; CONSUME(X);                                  // row R0+2 (primes pipeline)

    // ---- Steady state: X = converted row r+2. addY first, then consume
    //      row r+3 (LDS overlaps fin/addZ), then finish and store z(r). ----
#define STEP(Y0, Y1, Y2, Z0, Z1, Z2)                                          \
    do {                                                                      \
        addY<2, false>(Y0, X, W1);                                            \
        addY<1, false>(Y1, X, W1);                                            \
        addY<0, true >(Y2, X, W1);                                            \
        XP Xn; CONSUME(Xn);                                                   \
        YQ Qs = fin<SAFE>(Y0, (unsigned)(r + 1) < IMG_H, killE, lane);        \
        addZ<2, false>(Z0, Qs, W2);                                           \
        addZ<1, false>(Z1, Qs, W2);                                           \
        addZ<0, true >(Z2, Qs, W2);                                           \
        stz(orow, Z0);                                                        \
        orow += IMG_W; r++;                                                   \
        X = Xn;                                                               \
    } while (0)

#define STEPNL(Y0, Y1, Y2, Z0, Z1, Z2)                                        \
    do {                                                                      \
        addY<2, false>(Y0, X, W1);                                            \
        addY<1, false>(Y1, X, W1);                                            \
        addY<0, true >(Y2, X, W1);                                            \
        YQ Qs = fin<SAFE>(Y0, (unsigned)(r + 1) < IMG_H, killE, lane);        \
        addZ<2, false>(Z0, Qs, W2);                                           \
        addZ<1, false>(Z1, Qs, W2);                                           \
        addZ<0, true >(Z2, Qs, W2);                                           \
        stz(orow, Z0);                                                        \
        orow += IMG_W; r++;                                                   \
    } while (0)

#pragma unroll 1
    for (int i = 0; i < 21; i++) {                     // 63 rows
        STEP(ya, yb, yc, za, zb, zc);
        STEP(yb, yc, ya, zb, zc, za);
        STEP(yc, ya, yb, zc, za, zb);
    }
    STEPNL(ya, yb, yc, za, zb, zc);                    // row 64 (X already held)
#undef STEP
#undef STEPNL
#undef CONSUME
}

__global__ __launch_bounds__(WARPS_PER_CTA * 32, 4)
void conv2x_ring2(const float* __restrict__ x, const float* __restrict__ w1g,
                  const float* __restrict__ w2g, float* __restrict__ out)
{
    __shared__ __align__(16) char smem[WARPS_PER_CTA * WSMEM];   // 26112 B

    const int lane  = threadIdx.x & 31;
    const int wrp   = threadIdx.x >> 5;
    const int strip = blockIdx.x;                       // 0..7
    const int chunk = blockIdx.y * WARPS_PER_CTA + wrp; // 0..31
    const int c0 = strip * 256;
    const int R0 = chunk * ROWS;
    const bool lE = (strip == 0);
    const bool rE = (strip == STRIPS - 1);

    char* wb = smem + wrp * WSMEM;
    uint32_t wb_u = (uint32_t)__cvta_generic_to_shared(wb);

    const float* xb = x   + (size_t)blockIdx.z * ((size_t)IMG_H * IMG_W);
    float*       ob = out + (size_t)blockIdx.z * ((size_t)IMG_H * IMG_W);

    if (chunk != 0 && chunk != (IMG_H / ROWS) - 1)
        run<true >(wb, wb_u, xb, ob, w1g, w2g, c0, R0, lane, lE, rE);
    else
        run<false>(wb, wb_u, xb, ob, w1g, w2g, c0, R0, lane, lE, rE);
}

extern "C" void kernel_launch(void* const* d_in, const int* in_sizes, int n_in,
                              void* d_out, int out_size)
{
    const float* x  = (const float*)d_in[0];
    const float* w1 = (const float*)d_in[1];
    const float* w2 = (const float*)d_in[2];
    float* out = (float*)d_out;

    const int B = in_sizes[0] / (IMG_H * IMG_W);            // 16
    dim3 grid(STRIPS, (IMG_H / ROWS) / WARPS_PER_CTA, B);   // 8 x 8 x 16 = 1024
    conv2x_ring2<<<grid, WARPS_PER_CTA * 32>>>(x, w1, w2, out);
}